// round 9
// baseline (speedup 1.0000x reference)
#include <cuda_runtime.h>
#include <cuda_bf16.h>
#include <cstdint>

// Problem constants
#define NXg 512
#define NYg 512
#define NSENS 128
#define NT 2048
#define NPIX (NXg * NYg)

#define GROUP 8        // sensors staged per round (= warps per block)
#define ROUNDS (NSENS / GROUP)
#define WWIN 60        // window entries per (block,sensor); true span <= 56
#define EULL 5         // u64 per entry: 4 data + 1 pad -> bank-pair period 16

// Scratch: sensor data transposed to [s][t][8ch] (32B entries). 8 MB.
__device__ float4 g_scratch[NSENS * NT * 2];

// ---------------------------------------------------------------------------
// Prep kernel: transpose sensor_data [B=4][C=2][S=128][T=2048] -> [S][T][8]
// ---------------------------------------------------------------------------
__global__ __launch_bounds__(256) void das_transpose_kernel(
    const float* __restrict__ sd)
{
    int idx = blockIdx.x * blockDim.x + threadIdx.x;   // 0 .. 128*2048-1
    if (idx >= NSENS * NT) return;
    int s = idx >> 11;
    int t = idx & (NT - 1);

    const int bcStride = NSENS * NT;
    const float* base = sd + s * NT + t;

    float4 v0, v1;
    v0.x = base[0 * bcStride];
    v0.y = base[1 * bcStride];
    v0.z = base[2 * bcStride];
    v0.w = base[3 * bcStride];
    v1.x = base[4 * bcStride];
    v1.y = base[5 * bcStride];
    v1.z = base[6 * bcStride];
    v1.w = base[7 * bcStride];

    g_scratch[idx * 2 + 0] = v0;
    g_scratch[idx * 2 + 1] = v1;
}

// ---------------------------------------------------------------------------
// Main DAS kernel: 16x16 pixel tile per block. Per round, warp w stages the
// full 60-entry window of sensor (8r+w) into smem (40B-padded entries), then
// all warps gather 8 sensors via 4x LDS.64 + packed f32x2 accumulation.
// ---------------------------------------------------------------------------
__global__ __launch_bounds__(256, 6) void das_main_kernel(
    const int* __restrict__ sensor_xy,   // [128][2] int32
    float* __restrict__ out)             // [8][NPIX]
{
    __shared__ float4 smeta[NSENS];                       // cx, cy, tmin(bits)
    __shared__ unsigned long long swin[GROUP * WWIN * EULL];  // 19200 B

    const int tid  = threadIdx.x;        // 0..255
    const int lane = tid & 31;
    const int w    = tid >> 5;           // 0..7

    const int iy0 = blockIdx.x * 16;
    const int ix0 = blockIdx.y * 16;

    // XLA chain (bit-exact, validated R3): dis * fl(fl(1/VS)*fl(1/DT)).
    const float K = (1.0f / 1550.0f) * (1.0f / 2.5e-8f);

    // Per-sensor meta: position + window base (monotone chain => tmin <= t
    // for every tile pixel; validated R8, rel_err 0.0).
    if (tid < NSENS) {
        int2 xy = ((const int2*)sensor_xy)[tid];
        float cx = (float)xy.x, cy = (float)xy.y;
        float px = fminf(fmaxf(cx, (float)ix0), (float)(ix0 + 15));
        float py = fminf(fmaxf(cy, (float)iy0), (float)(iy0 + 15));
        float dx = __fmul_rn(cx - px, 1e-4f);
        float dy = __fmul_rn(cy - py, 1e-4f);
        float dis = __fsqrt_rn(__fadd_rn(__fmul_rn(dx, dx), __fmul_rn(dy, dy)));
        int tmin = (int)__fmul_rn(dis, K);           // tmin + 59 < 2048 always
        smeta[tid] = make_float4(cx, cy, __int_as_float(tmin), 0.0f);
    }

    // Warp patch: 8 iy x 4 ix (warp t-span <= 21).
    const int ly = lane & 7;
    const int lx = lane >> 3;
    const int wy = w & 1;
    const int wx = w >> 1;
    const int iy = iy0 + wy * 8 + ly;
    const int ix = ix0 + wx * 4 + lx;
    const float fix = (float)ix;
    const float fiy = (float)iy;

    // Packed accumulators (add.rn.f32x2 = two independent IEEE RN adds).
    unsigned long long a0 = 0ull, a1 = 0ull, a2 = 0ull, a3 = 0ull;

    __syncthreads();   // smeta ready

    #pragma unroll 1
    for (int r = 0; r < ROUNDS; ++r) {
        // ---- Stage: warp w copies sensor (8r+w)'s window. 120 x 16B halves,
        //      lane handles halves lane, lane+32, lane+64, lane+96 (<120). ----
        {
            const int s = r * GROUP + w;
            const int tmn = __float_as_int(smeta[s].z);    // LDS broadcast
            const ulonglong2* __restrict__ src =
                (const ulonglong2*)g_scratch + ((((unsigned)s << 11) + (unsigned)tmn) << 1);
            #pragma unroll
            for (int k = 0; k < 4; ++k) {
                int f = lane + k * 32;
                if (k < 3 || lane < 24) {                  // f < 120
                    ulonglong2 v = __ldg(src + f);
                    int e = f >> 1, h = f & 1;
                    int wb = (w * WWIN + e) * EULL + (h << 1);
                    swin[wb + 0] = v.x;
                    swin[wb + 1] = v.y;
                }
            }
        }
        __syncthreads();   // windows visible

        // ---- Gather 8 sensors from smem ----
        #pragma unroll
        for (int g = 0; g < GROUP; ++g) {
            float4 m = smeta[r * GROUP + g];               // LDS.128 broadcast
            float dx = __fmul_rn(m.x - fix, 1e-4f);
            float dy = __fmul_rn(m.y - fiy, 1e-4f);
            float dis = __fsqrt_rn(__fadd_rn(__fmul_rn(dx, dx), __fmul_rn(dy, dy)));
            int t = (int)__fmul_rn(dis, K);
            int tloc = t - __float_as_int(m.z);
            int wb = (g * WWIN + tloc) * EULL;

            unsigned long long v0 = swin[wb + 0];
            unsigned long long v1 = swin[wb + 1];
            unsigned long long v2 = swin[wb + 2];
            unsigned long long v3 = swin[wb + 3];
            asm("add.rn.f32x2 %0, %0, %1;" : "+l"(a0) : "l"(v0));
            asm("add.rn.f32x2 %0, %0, %1;" : "+l"(a1) : "l"(v1));
            asm("add.rn.f32x2 %0, %0, %1;" : "+l"(a2) : "l"(v2));
            asm("add.rn.f32x2 %0, %0, %1;" : "+l"(a3) : "l"(v3));
        }
        __syncthreads();   // gathers done before next round overwrites
    }

    const int p = ix * NYg + iy;
    unsigned lo, hi;
    asm("mov.b64 {%0,%1}, %2;" : "=r"(lo), "=r"(hi) : "l"(a0));
    out[0 * NPIX + p] = __uint_as_float(lo);
    out[1 * NPIX + p] = __uint_as_float(hi);
    asm("mov.b64 {%0,%1}, %2;" : "=r"(lo), "=r"(hi) : "l"(a1));
    out[2 * NPIX + p] = __uint_as_float(lo);
    out[3 * NPIX + p] = __uint_as_float(hi);
    asm("mov.b64 {%0,%1}, %2;" : "=r"(lo), "=r"(hi) : "l"(a2));
    out[4 * NPIX + p] = __uint_as_float(lo);
    out[5 * NPIX + p] = __uint_as_float(hi);
    asm("mov.b64 {%0,%1}, %2;" : "=r"(lo), "=r"(hi) : "l"(a3));
    out[6 * NPIX + p] = __uint_as_float(lo);
    out[7 * NPIX + p] = __uint_as_float(hi);
}

// ---------------------------------------------------------------------------
// Entry point
// ---------------------------------------------------------------------------
extern "C" void kernel_launch(void* const* d_in, const int* in_sizes, int n_in,
                              void* d_out, int out_size)
{
    const float* sensor_data = (const float*)d_in[0];   // (4,2,128,2048) f32
    const int*   sensor_xy   = (const int*)d_in[1];     // (128,2) i32
    float*       out         = (float*)d_out;           // (4,2,512,512) f32

    das_transpose_kernel<<<(NSENS * NT + 255) / 256, 256>>>(sensor_data);

    dim3 block(256);
    dim3 grid(NYg / 16, NXg / 16);
    das_main_kernel<<<grid, block>>>(sensor_xy, out);
}

// round 10
// speedup vs baseline: 1.2042x; 1.2042x over previous
#include <cuda_runtime.h>
#include <cuda_bf16.h>
#include <cstdint>

// Problem constants
#define NXg 512
#define NYg 512
#define NSENS 128
#define NT 2048
#define NPIX (NXg * NYg)

// Two half-channel scratch arrays: [s][t][4ch] as one float4 per (s,t).
// 4 MB each; a 128B line holds 8 consecutive t entries -> low line overfetch.
__device__ float4 g_scratchA[NSENS * NT];   // channels 0..3
__device__ float4 g_scratchB[NSENS * NT];   // channels 4..7

// ---------------------------------------------------------------------------
// Prep kernel: transpose sensor_data [B=4][C=2][S=128][T=2048] -> 2x [S][T][4]
// Each thread handles 4 consecutive t: 8x LDG.128 in, 8x STG.128 out,
// register 4x4 transpose. Fully coalesced both sides.
// ---------------------------------------------------------------------------
__global__ __launch_bounds__(256) void das_transpose_kernel(
    const float* __restrict__ sd)
{
    int idx = blockIdx.x * blockDim.x + threadIdx.x;   // 0 .. 128*512-1
    if (idx >= NSENS * (NT / 4)) return;
    int s  = idx >> 9;                 // sensor
    int tq = (idx & 511) << 2;         // t base (multiple of 4)

    const int bcStride = NSENS * NT;   // 262144 floats per (b,c) plane
    const float* base = sd + s * NT + tq;

    float4 c0 = *(const float4*)(base + 0 * bcStride);
    float4 c1 = *(const float4*)(base + 1 * bcStride);
    float4 c2 = *(const float4*)(base + 2 * bcStride);
    float4 c3 = *(const float4*)(base + 3 * bcStride);
    float4 c4 = *(const float4*)(base + 4 * bcStride);
    float4 c5 = *(const float4*)(base + 5 * bcStride);
    float4 c6 = *(const float4*)(base + 6 * bcStride);
    float4 c7 = *(const float4*)(base + 7 * bcStride);

    unsigned e = ((unsigned)s << 11) + (unsigned)tq;
    g_scratchA[e + 0] = make_float4(c0.x, c1.x, c2.x, c3.x);
    g_scratchA[e + 1] = make_float4(c0.y, c1.y, c2.y, c3.y);
    g_scratchA[e + 2] = make_float4(c0.z, c1.z, c2.z, c3.z);
    g_scratchA[e + 3] = make_float4(c0.w, c1.w, c2.w, c3.w);
    g_scratchB[e + 0] = make_float4(c4.x, c5.x, c6.x, c7.x);
    g_scratchB[e + 1] = make_float4(c4.y, c5.y, c6.y, c7.y);
    g_scratchB[e + 2] = make_float4(c4.z, c5.z, c6.z, c7.z);
    g_scratchB[e + 3] = make_float4(c4.w, c5.w, c6.w, c7.w);
}

// ---------------------------------------------------------------------------
// Main DAS kernel: one thread per pixel, 128-sensor loop.
// 128-thread blocks (4 warps, 16iy x 8ix tile) to halve wave-tail imbalance;
// warp patch stays 8(iy) x 4(ix) — the validated minimum-span geometry.
// ---------------------------------------------------------------------------
__global__ __launch_bounds__(128) void das_main_kernel(
    const int* __restrict__ sensor_xy,   // [128][2] int32
    float* __restrict__ out)             // [8][NPIX]
{
    __shared__ float2 sxy[NSENS];

    const int tid  = threadIdx.x;        // 0..127
    const int lane = tid & 31;
    const int w    = tid >> 5;           // 0..3

    {
        int2 xy = ((const int2*)sensor_xy)[tid];
        sxy[tid] = make_float2((float)xy.x, (float)xy.y);
    }
    __syncthreads();

    // Warp patch: 8 iy x 4 ix. Warps tile 2(iy) x 2(ix) over a 16x8 tile.
    const int ly = lane & 7;
    const int lx = lane >> 3;
    const int wy = w & 1;
    const int wx = w >> 1;

    const int iy = blockIdx.x * 16 + wy * 8 + ly;
    const int ix = blockIdx.y * 8 + wx * 4 + lx;

    const float fix = (float)ix;
    const float fiy = (float)iy;

    // XLA chain (bit-exact, validated R3): dis * fl(fl(1/VS)*fl(1/DT)).
    const float K = (1.0f / 1550.0f) * (1.0f / 2.5e-8f);

    float4 a0 = make_float4(0.f, 0.f, 0.f, 0.f);
    float4 a1 = make_float4(0.f, 0.f, 0.f, 0.f);

    #pragma unroll 4
    for (int s = 0; s < NSENS; ++s) {
        float2 c = sxy[s];
        float dx = __fmul_rn(c.x - fix, 1e-4f);
        float dy = __fmul_rn(c.y - fiy, 1e-4f);
        float r2 = __fadd_rn(__fmul_rn(dx, dx), __fmul_rn(dy, dy));
        float dis = __fsqrt_rn(r2);
        int t = (int)__fmul_rn(dis, K);

        unsigned off = ((unsigned)s << 11) + (unsigned)t;
        float4 v0 = __ldg(&g_scratchA[off]);
        float4 v1 = __ldg(&g_scratchB[off]);
        a0.x += v0.x; a0.y += v0.y; a0.z += v0.z; a0.w += v0.w;
        a1.x += v1.x; a1.y += v1.y; a1.z += v1.z; a1.w += v1.w;
    }

    const int p = ix * NYg + iy;
    out[0 * NPIX + p] = a0.x;
    out[1 * NPIX + p] = a0.y;
    out[2 * NPIX + p] = a0.z;
    out[3 * NPIX + p] = a0.w;
    out[4 * NPIX + p] = a1.x;
    out[5 * NPIX + p] = a1.y;
    out[6 * NPIX + p] = a1.z;
    out[7 * NPIX + p] = a1.w;
}

// ---------------------------------------------------------------------------
// Entry point
// ---------------------------------------------------------------------------
extern "C" void kernel_launch(void* const* d_in, const int* in_sizes, int n_in,
                              void* d_out, int out_size)
{
    const float* sensor_data = (const float*)d_in[0];   // (4,2,128,2048) f32
    const int*   sensor_xy   = (const int*)d_in[1];     // (128,2) i32
    float*       out         = (float*)d_out;           // (4,2,512,512) f32

    das_transpose_kernel<<<(NSENS * (NT / 4) + 255) / 256, 256>>>(sensor_data);

    dim3 block(128);
    dim3 grid(NYg / 16, NXg / 8);
    das_main_kernel<<<grid, block>>>(sensor_xy, out);
}